// round 12
// baseline (speedup 1.0000x reference)
#include <cuda_runtime.h>
#include <cuda_bf16.h>
#include <cstdint>
#include <math.h>

// Problem constants
#define B_DIM 8
#define C_DIM 256
#define S_DIM 8192
#define N_PTS 65536
#define N_CODES 1024
#define Z_ELEMS 16777216
#define BATCH_STRIDE 2097152

// Output layout (concatenated, fp32)
#define ZQ_OFF 0
#define IDX_OFF 16777216
#define LOSS_OFF 16842752
#define PERP_OFF 16842753

#define ZROW 68                          // int32 words per smem row (64 + 4 pad)
#define GEMM_SMEM (3*128*ZROW*4)         // Z8 + 2 E8 buffers = 104448 B
#define PREPZ_SMEM (256*68*4)            // padded fp32 [k][m] tile
#define EXACT_SMEM (256*64*4)            // fp32 [k][m] tile (frozen layout)
#define CAND_CAP 8192

typedef unsigned long long ull;

// Scratch (device globals; allocation is forbidden)
__device__ float  g_e2[N_CODES];         // ||e_j||^2 (frozen chain)
__device__ float  g_se[N_CODES];         // e int8 scale
__device__ float  g_A[N_PTS];            // sum z^2 (frozen chain)
__device__ float  g_U[N_PTS];            // sum |z|
__device__ float  g_sz[N_PTS];           // z int8 scale
__device__ int    g_idx[N_PTS];
__device__ float  g_cnt[N_CODES];
__device__ double g_loss;
__device__ int    g_z8[N_PTS * 64];      // packed int8 z, [pt][kword]
__device__ int    g_e8[N_CODES * 64];    // packed int8 e, [code][kword]
__device__ int    g_qemax_bits = 0;      // max over codes of se/2 (float bits)
__device__ int    g_Uemax_bits = 0;      // max over codes of sum|e| (float bits)
__device__ int2   g_slots[(size_t)N_PTS * 16]; // 8 chunks x top-2 {v_bits, j}

__device__ __forceinline__ void cp16(unsigned saddr, const void* g) {
    asm volatile("cp.async.cg.shared.global [%0], [%1], 16;" :: "r"(saddr), "l"(g));
}
#define CP_COMMIT() asm volatile("cp.async.commit_group;")
#define CP_WAIT0()  asm volatile("cp.async.wait_group 0;")
#define CP_WAIT1()  asm volatile("cp.async.wait_group 1;")

// ---------------------------------------------------------------------------
// K1: per-code ||e||^2 (FROZEN chain), int8 scale + pack, Ue/qe maxes.
// grid 128 x 256: warp per code.
// ---------------------------------------------------------------------------
__global__ void vq_prep_e(const float* __restrict__ embed) {
    int t = threadIdx.x, lane = t & 31;
    int code = blockIdx.x * 8 + (t >> 5);
    const float* row = embed + code * C_DIM;

    // frozen ||e||^2 chain (bit-identical to R4/R8 passing runs)
    float s = 0.f;
#pragma unroll
    for (int q = 0; q < 8; ++q) { float e = row[lane + q * 32]; s = fmaf(e, e, s); }
#pragma unroll
    for (int off = 16; off > 0; off >>= 1) s += __shfl_down_sync(0xffffffffu, s, off);
    if (lane == 0) g_e2[code] = s;

    // max|e| and sum|e| (bound-only; slack covers fp noise)
    float mx = 0.f, ua = 0.f;
#pragma unroll
    for (int q = 0; q < 8; ++q) {
        float e = fabsf(row[lane + q * 32]);
        mx = fmaxf(mx, e);
        ua += e;
    }
#pragma unroll
    for (int off = 16; off > 0; off >>= 1) {
        mx = fmaxf(mx, __shfl_down_sync(0xffffffffu, mx, off));
        ua += __shfl_down_sync(0xffffffffu, ua, off);
    }
    if (lane == 0) {
        g_se[code] = mx * (1.f / 127.f);
        atomicMax(&g_qemax_bits, __float_as_int(mx * (0.5f / 127.f)));
        atomicMax(&g_Uemax_bits, __float_as_int(ua));
    }
    float mxa = __shfl_sync(0xffffffffu, mx, 0);
    float inv = (mxa > 0.f) ? (127.f / mxa) : 0.f;
    // pack: lane handles elems lane*8 .. +7 -> words code*64 + lane*2, +1
#pragma unroll
    for (int w = 0; w < 2; ++w) {
        int k0 = lane * 8 + w * 4;
        int b0 = __float2int_rn(row[k0 + 0] * inv) & 255;
        int b1 = __float2int_rn(row[k0 + 1] * inv) & 255;
        int b2 = __float2int_rn(row[k0 + 2] * inv) & 255;
        int b3 = __float2int_rn(row[k0 + 3] * inv) & 255;
        g_e8[code * 64 + lane * 2 + w] = b0 | (b1 << 8) | (b2 << 16) | (b3 << 24);
    }
    if (blockIdx.x == 0) {
        for (int i = t; i < N_CODES; i += 256) g_cnt[i] = 0.f;
        if (t == 0) g_loss = 0.0;
    }
}

// ---------------------------------------------------------------------------
// K2: per-point A (FROZEN chain), U, max|z|, int8 pack. 64 pts/block.
// ---------------------------------------------------------------------------
__global__ void vq_prep_z(const float* __restrict__ z) {
    extern __shared__ float Ze[];          // [k 256][stride 68]
    __shared__ float sInv[64];
    const int t  = threadIdx.x;
    const int tb = blockIdx.x;
    const int b  = tb >> 7;
    const int s0 = (tb & 127) * 64;
    const float* zb = z + (size_t)b * BATCH_STRIDE + s0;

#pragma unroll
    for (int i = 0; i < 16; ++i) {
        int lin = i * 256 + t;
        int k = lin >> 4, mq = lin & 15;
        *(float4*)(Ze + k * 68 + mq * 4) = *(const float4*)(zb + (size_t)k * S_DIM + mq * 4);
    }
    __syncthreads();

    if (t < 64) {
        float a = 0.f, u = 0.f, mx = 0.f;
#pragma unroll 8
        for (int k = 0; k < 256; ++k) {
            float v = Ze[k * 68 + t];
            a = fmaf(v, v, a);              // FROZEN A chain
            u += fabsf(v);
            mx = fmaxf(mx, fabsf(v));
        }
        int p = tb * 64 + t;
        g_A[p] = a;
        g_U[p] = u;
        g_sz[p] = mx * (1.f / 127.f);
        sInv[t] = (mx > 0.f) ? (127.f / mx) : 0.f;
    }
    __syncthreads();

    // pack 64 pts x 64 words; thread does 16 words
#pragma unroll
    for (int i = 0; i < 16; ++i) {
        int w = i * 256 + t;
        int pt = w >> 6, kw = w & 63;
        float inv = sInv[pt];
        int k0 = kw * 4;
        int b0 = __float2int_rn(Ze[(k0 + 0) * 68 + pt] * inv) & 255;
        int b1 = __float2int_rn(Ze[(k0 + 1) * 68 + pt] * inv) & 255;
        int b2 = __float2int_rn(Ze[(k0 + 2) * 68 + pt] * inv) & 255;
        int b3 = __float2int_rn(Ze[(k0 + 3) * 68 + pt] * inv) & 255;
        g_z8[(tb * 64 + pt) * 64 + kw] = b0 | (b1 << 8) | (b2 << 16) | (b3 << 24);
    }
}

// ---------------------------------------------------------------------------
// K3: int8 DP4A scoring GEMM + per-chunk top-2 slots.
// grid (512, 2): 128 pts x 512 codes per block, 4 chunks of 128 codes.
// 256 threads as 16x16; thread: pts {tx+q*16}, codes {ty+r*16} per chunk.
// ---------------------------------------------------------------------------
__global__ void __launch_bounds__(256)
vq_gemm_i8() {
    extern __shared__ int sm[];
    int* Z8 = sm;                                   // [128][68]
    int* EB[2] = { sm + 128 * ZROW, sm + 2 * 128 * ZROW };

    const int t  = threadIdx.x;
    const int tx = t & 15;
    const int ty = t >> 4;
    const int ptt = blockIdx.x;
    const int cy  = blockIdx.y;
    const int pbase = ptt * 128;
    const int cbase = cy * 512;

    const unsigned sZ  = (unsigned)__cvta_generic_to_shared(Z8);
    const unsigned sE0 = (unsigned)__cvta_generic_to_shared(EB[0]);
    const unsigned sE1 = (unsigned)__cvta_generic_to_shared(EB[1]);

    // Z tile + E chunk 0 (group 0); E chunk 1 (group 1)
#pragma unroll
    for (int i = 0; i < 8; ++i) {
        int lin = i * 256 + t, r = lin >> 4, seg = lin & 15;
        cp16(sZ + (unsigned)(r * ZROW + seg * 4) * 4, g_z8 + (size_t)(pbase + r) * 64 + seg * 4);
    }
#pragma unroll
    for (int i = 0; i < 8; ++i) {
        int lin = i * 256 + t, r = lin >> 4, seg = lin & 15;
        cp16(sE0 + (unsigned)(r * ZROW + seg * 4) * 4, g_e8 + (size_t)(cbase + r) * 64 + seg * 4);
    }
    CP_COMMIT();
#pragma unroll
    for (int i = 0; i < 8; ++i) {
        int lin = i * 256 + t, r = lin >> 4, seg = lin & 15;
        cp16(sE1 + (unsigned)(r * ZROW + seg * 4) * 4, g_e8 + (size_t)(cbase + 128 + r) * 64 + seg * 4);
    }
    CP_COMMIT();

    float szq[8];
#pragma unroll
    for (int q = 0; q < 8; ++q) szq[q] = __ldg(&g_sz[pbase + tx + q * 16]);

    for (int ch = 0; ch < 4; ++ch) {
        if (ch < 3) CP_WAIT1(); else CP_WAIT0();
        __syncthreads();
        const int* Ec = EB[ch & 1];

        int acc[8][8];
#pragma unroll
        for (int q = 0; q < 8; ++q)
#pragma unroll
            for (int r = 0; r < 8; ++r) acc[q][r] = 0;

#pragma unroll 2
        for (int kw2 = 0; kw2 < 32; ++kw2) {
            int2 a[8], e[8];
#pragma unroll
            for (int q = 0; q < 8; ++q)
                a[q] = *(const int2*)(Z8 + (tx + q * 16) * ZROW + kw2 * 2);
#pragma unroll
            for (int r = 0; r < 8; ++r)
                e[r] = *(const int2*)(Ec + (ty + r * 16) * ZROW + kw2 * 2);
#pragma unroll
            for (int q = 0; q < 8; ++q)
#pragma unroll
                for (int r = 0; r < 8; ++r) {
                    acc[q][r] = __dp4a(a[q].x, e[r].x, acc[q][r]);
                    acc[q][r] = __dp4a(a[q].y, e[r].y, acc[q][r]);
                }
        }

        // per-thread top-2 over its 8 codes, per point
        float v1[8], v2[8]; int j1[8], j2[8];
#pragma unroll
        for (int q = 0; q < 8; ++q) { v1[q] = INFINITY; v2[q] = INFINITY; j1[q] = 0; j2[q] = 0; }
#pragma unroll
        for (int r = 0; r < 8; ++r) {
            int j = cbase + ch * 128 + ty + r * 16;
            float se = __ldg(&g_se[j]);
            float Bj = __ldg(&g_e2[j]);
#pragma unroll
            for (int q = 0; q < 8; ++q) {
                float v = fmaf(-2.f * szq[q] * se, (float)acc[q][r], Bj);
                if (v < v1[q])      { v2[q] = v1[q]; j2[q] = j1[q]; v1[q] = v; j1[q] = j; }
                else if (v < v2[q]) { v2[q] = v;  j2[q] = j; }
            }
        }
        __syncthreads();                       // compute done before scratch reuse

        int2* sc = (int2*)EB[ch & 1];          // 128 pts x 16 ty x 2 = 32KB
#pragma unroll
        for (int q = 0; q < 8; ++q) {
            int pl = tx + q * 16;
            sc[(pl * 16 + ty) * 2]     = make_int2(__float_as_int(v1[q]), j1[q]);
            sc[(pl * 16 + ty) * 2 + 1] = make_int2(__float_as_int(v2[q]), j2[q]);
        }
        __syncthreads();

        if (t < 128) {
            float b1 = INFINITY, b2 = INFINITY; int i1 = 0, i2 = 0;
#pragma unroll
            for (int y = 0; y < 16; ++y) {
#pragma unroll
                for (int e2i = 0; e2i < 2; ++e2i) {
                    int2 ev = sc[(t * 16 + y) * 2 + e2i];
                    float v = __int_as_float(ev.x);
                    if (v < b1)      { b2 = b1; i2 = i1; b1 = v; i1 = ev.y; }
                    else if (v < b2) { b2 = v;  i2 = ev.y; }
                }
            }
            size_t base = (size_t)(pbase + t) * 16 + (cy * 4 + ch) * 2;
            g_slots[base]     = make_int2(__float_as_int(b1), i1);
            g_slots[base + 1] = make_int2(__float_as_int(b2), i2);
        }
        __syncthreads();

        if (ch < 2) {                          // prefetch E(ch+2) into freed buffer
            unsigned sb = (ch & 1) ? sE1 : sE0;
#pragma unroll
            for (int i = 0; i < 8; ++i) {
                int lin = i * 256 + t, r = lin >> 4, seg = lin & 15;
                cp16(sb + (unsigned)(r * ZROW + seg * 4) * 4,
                     g_e8 + (size_t)(cbase + (ch + 2) * 128 + r) * 64 + seg * 4);
            }
            CP_COMMIT();
        }
    }
}

// ---------------------------------------------------------------------------
// K4: sound candidate selection + exact (FROZEN) recheck, cooperative drain.
// ---------------------------------------------------------------------------
__global__ void vq_exact(const float* __restrict__ z,
                         const float* __restrict__ embed,
                         float* __restrict__ out) {
    extern __shared__ float Ze[];          // [k 256][m 64] (frozen layout)
    __shared__ unsigned short cand[CAND_CAP];
    __shared__ int cnt;
    __shared__ ull key[64];
    __shared__ float sA[64];

    const int t  = threadIdx.x;
    const int tb = blockIdx.x;
    const int b  = tb >> 7;
    const int s0 = (tb & 127) * 64;
    const float* zb = z + (size_t)b * BATCH_STRIDE + s0;

#pragma unroll
    for (int i = 0; i < 16; ++i) {
        int lin = i * 256 + t;
        int k = lin >> 4, mq = lin & 15;
        *(float4*)(Ze + k * 64 + mq * 4) = *(const float4*)(zb + (size_t)k * S_DIM + mq * 4);
    }
    if (t == 0) cnt = 0;
    if (t < 64) { key[t] = ~0ull; sA[t] = g_A[tb * 64 + t]; }
    __syncthreads();

    if (t < 64) {
        const int p = tb * 64 + t;
        const float A = sA[t];
        const int2* sl = g_slots + (size_t)p * 16;

        float gmin = INFINITY;
#pragma unroll
        for (int c = 0; c < 8; ++c)
            gmin = fminf(gmin, __int_as_float(__ldg((const int*)&sl[2 * c].x)));

        // sound tau: 2*(Ue_max*qz + U*qe_max + 256*qz*qe_max) + slack
        float qz = 0.5f * g_sz[p];
        float qe = __int_as_float(g_qemax_bits);
        float Ue = __int_as_float(g_Uemax_bits);
        float err = 2.f * (fmaf(Ue, qz, g_U[p] * qe) + 256.f * qz * qe);
        const float tau = gmin + err + 3e-4f;

        for (int c = 0; c < 8; ++c) {
            int2 s1 = __ldg((const int2*)&sl[2 * c]);
            int2 s2 = __ldg((const int2*)&sl[2 * c + 1]);
            if (__int_as_float(s2.x) <= tau) {
                // fallback: all 128 codes of this chunk are candidates
                int base = atomicAdd(&cnt, 128);
                if (base + 128 <= CAND_CAP) {
                    for (int q = 0; q < 128; ++q)
                        cand[base + q] = (unsigned short)((t << 10) | (c * 128 + q));
                } else {
                    for (int q = 0; q < 128; ++q) {
                        int j = c * 128 + q;
                        float m = 0.f;
                        const float* er = embed + (size_t)j * C_DIM;
#pragma unroll 8
                        for (int k = 0; k < 256; ++k)
                            m = fmaf(Ze[k * 64 + t], __ldg(er + k), m);
                        float d = __fadd_rn(__fadd_rn(A, g_e2[j]), -2.0f * m);
                        atomicMin(&key[t], ((ull)(unsigned)__float_as_int(d) << 32) | (unsigned)j);
                    }
                }
            } else if (__int_as_float(s1.x) <= tau) {
                int base = atomicAdd(&cnt, 1);
                if (base < CAND_CAP) {
                    cand[base] = (unsigned short)((t << 10) | s1.y);
                } else {
                    int j = s1.y;
                    float m = 0.f;
                    const float* er = embed + (size_t)j * C_DIM;
#pragma unroll 8
                    for (int k = 0; k < 256; ++k)
                        m = fmaf(Ze[k * 64 + t], __ldg(er + k), m);
                    float d = __fadd_rn(__fadd_rn(A, g_e2[j]), -2.0f * m);
                    atomicMin(&key[t], ((ull)(unsigned)__float_as_int(d) << 32) | (unsigned)j);
                }
            }
        }
    }
    __syncthreads();

    int n = min(cnt, CAND_CAP);
    for (int i = t; i < n; i += 256) {
        int e  = cand[i];
        int pl = e >> 10, j = e & 1023;
        float m = 0.f;                         // FROZEN exact chain
        const float* er = embed + (size_t)j * C_DIM;
#pragma unroll 8
        for (int k = 0; k < 256; ++k)
            m = fmaf(Ze[k * 64 + pl], __ldg(er + k), m);
        float d = __fadd_rn(__fadd_rn(sA[pl], g_e2[j]), -2.0f * m);
        // d > 0 (A ~ 256): float-bit order == numeric; low 32 = j -> lexicographic
        atomicMin(&key[pl], ((ull)(unsigned)__float_as_int(d) << 32) | (unsigned)j);
    }
    __syncthreads();

    if (t < 64) {
        int bi = (int)(key[t] & 0xFFFFFFFFull);
        int p = tb * 64 + t;
        g_idx[p] = bi;
        out[IDX_OFF + p] = (float)bi;
    }
}

// ---------------------------------------------------------------------------
// K5: z_q = fl(z + fl(e - z)), commitment loss, histogram. (FROZEN)
// ---------------------------------------------------------------------------
__global__ void vq_quantize_kernel(const float* __restrict__ z,
                                   const float* __restrict__ embed,
                                   float* __restrict__ out) {
    __shared__ int    sidx[64];
    __shared__ double red[256];

    const int t  = threadIdx.x;
    const int tb = blockIdx.x;
    const int b  = tb >> 7;
    const int s0 = (tb & 127) * 64;

    if (t < 64) {
        int id = g_idx[tb * 64 + t];
        sidx[t] = id;
        atomicAdd(&g_cnt[id], 1.0f);
    }
    __syncthreads();

    const float* zb = z   + (size_t)b * BATCH_STRIDE + s0;
    float*       qb = out + ZQ_OFF + (size_t)b * BATCH_STRIDE + s0;

    double lacc = 0.0;
#pragma unroll
    for (int i = 0; i < 16; ++i) {
        int lin = i * 256 + t;
        int c = lin >> 4, mq = lin & 15;
        float4 zv = *(const float4*)(zb + (size_t)c * S_DIM + mq * 4);
        float4 ev;
        ev.x = __ldg(embed + (size_t)sidx[mq * 4 + 0] * C_DIM + c);
        ev.y = __ldg(embed + (size_t)sidx[mq * 4 + 1] * C_DIM + c);
        ev.z = __ldg(embed + (size_t)sidx[mq * 4 + 2] * C_DIM + c);
        ev.w = __ldg(embed + (size_t)sidx[mq * 4 + 3] * C_DIM + c);
        float dx = __fadd_rn(ev.x, -zv.x);
        float dy = __fadd_rn(ev.y, -zv.y);
        float dz = __fadd_rn(ev.z, -zv.z);
        float dw = __fadd_rn(ev.w, -zv.w);
        float4 qv;
        qv.x = __fadd_rn(zv.x, dx);
        qv.y = __fadd_rn(zv.y, dy);
        qv.z = __fadd_rn(zv.z, dz);
        qv.w = __fadd_rn(zv.w, dw);
        *(float4*)(qb + (size_t)c * S_DIM + mq * 4) = qv;
        lacc += (double)(dx * dx) + (double)(dy * dy)
              + (double)(dz * dz) + (double)(dw * dw);
    }

    red[t] = lacc;
    __syncthreads();
    for (int off = 128; off > 0; off >>= 1) {
        if (t < off) red[t] += red[t + off];
        __syncthreads();
    }
    if (t == 0) atomicAdd(&g_loss, red[0]);
}

// ---------------------------------------------------------------------------
// K6: finalize loss + perplexity.
// ---------------------------------------------------------------------------
__global__ void vq_finalize_kernel(float* __restrict__ out) {
    __shared__ float sred[1024];
    int t = threadIdx.x;
    float p = g_cnt[t] * (1.0f / (float)N_PTS);
    sred[t] = p * logf(p + 1e-10f);
    __syncthreads();
    for (int off = 512; off > 0; off >>= 1) {
        if (t < off) sred[t] += sred[t + off];
        __syncthreads();
    }
    if (t == 0) {
        out[PERP_OFF] = expf(-sred[0]);
        out[LOSS_OFF] = 0.25f * (float)(g_loss / (double)Z_ELEMS);
    }
}

// ---------------------------------------------------------------------------
extern "C" void kernel_launch(void* const* d_in, const int* in_sizes, int n_in,
                              void* d_out, int out_size) {
    const float* z     = (const float*)d_in[0];
    const float* embed = (const float*)d_in[1];
    float* out = (float*)d_out;

    cudaFuncSetAttribute(vq_gemm_i8, cudaFuncAttributeMaxDynamicSharedMemorySize, GEMM_SMEM);
    cudaFuncSetAttribute(vq_prep_z,  cudaFuncAttributeMaxDynamicSharedMemorySize, PREPZ_SMEM);
    cudaFuncSetAttribute(vq_exact,   cudaFuncAttributeMaxDynamicSharedMemorySize, EXACT_SMEM);

    vq_prep_e<<<128, 256>>>(embed);
    vq_prep_z<<<1024, 256, PREPZ_SMEM>>>(z);
    vq_gemm_i8<<<dim3(512, 2), 256, GEMM_SMEM>>>();
    vq_exact<<<1024, 256, EXACT_SMEM>>>(z, embed, out);
    vq_quantize_kernel<<<1024, 256>>>(z, embed, out);
    vq_finalize_kernel<<<1, 1024>>>(out);
}

// round 13
// speedup vs baseline: 2.3265x; 2.3265x over previous
#include <cuda_runtime.h>
#include <cuda_fp16.h>
#include <cstdint>
#include <math.h>

// Problem constants
#define B_DIM 8
#define C_DIM 256
#define S_DIM 8192
#define N_PTS 65536
#define N_CODES 1024
#define Z_ELEMS 16777216
#define BATCH_STRIDE 2097152

// Output layout (concatenated, fp32)
#define ZQ_OFF 0
#define IDX_OFF 16777216
#define LOSS_OFF 16842752
#define PERP_OFF 16842753

#define ZPAD 132                          // half2 per k2 row (128 + 4 pad)
#define GEMM_SMEM (2*128*ZPAD*4)          // Zs + Es = 135168 B
#define PREPZ_SMEM (256*68*4)             // padded fp32 [k][m] tile
#define EXACT_SMEM (256*64*4)             // fp32 [k][m] tile (frozen layout)
#define CAND_CAP 8192

typedef unsigned long long ull;

// Scratch (device globals; runtime allocation forbidden)
__device__ float  g_e2[N_CODES];          // ||e_j||^2 (frozen chain)
__device__ float  g_A[N_PTS];             // sum z^2 (frozen chain)
__device__ float  g_U[N_PTS];             // sum |z|
__device__ int    g_idx[N_PTS];
__device__ float  g_cnt[N_CODES];
__device__ double g_loss;
__device__ int    g_emax_bits = 0;        // max over codes of max|e| (float bits)
__device__ __half g_zh[(size_t)N_PTS * C_DIM];    // z fp16, [pt][k]   (32MB)
__device__ __half g_eh[N_CODES * C_DIM];          // e fp16, [code][k] (512KB)
__device__ __half g_v[(size_t)N_PTS * N_CODES];   // approx scores     (128MB)

// ---------------------------------------------------------------------------
// K1: per-code ||e||^2 (FROZEN chain), fp16 copy, emax. grid 128 x 256.
// ---------------------------------------------------------------------------
__global__ void vq_prep_e(const float* __restrict__ embed) {
    int t = threadIdx.x, lane = t & 31;
    int code = blockIdx.x * 8 + (t >> 5);
    const float* row = embed + code * C_DIM;

    float s = 0.f;                         // FROZEN ||e||^2 chain
#pragma unroll
    for (int q = 0; q < 8; ++q) { float e = row[lane + q * 32]; s = fmaf(e, e, s); }
#pragma unroll
    for (int off = 16; off > 0; off >>= 1) s += __shfl_down_sync(0xffffffffu, s, off);
    if (lane == 0) g_e2[code] = s;

    float mx = 0.f;
#pragma unroll
    for (int q = 0; q < 8; ++q) mx = fmaxf(mx, fabsf(row[lane + q * 32]));
#pragma unroll
    for (int off = 16; off > 0; off >>= 1)
        mx = fmaxf(mx, __shfl_down_sync(0xffffffffu, mx, off));
    if (lane == 0) atomicMax(&g_emax_bits, __float_as_int(mx));

    // fp16 copy: lane handles k = lane*8..+7
    {
        __half2 h[4];
#pragma unroll
        for (int j = 0; j < 4; ++j)
            h[j] = __floats2half2_rn(row[lane * 8 + 2 * j], row[lane * 8 + 2 * j + 1]);
        *(uint4*)(g_eh + (size_t)code * C_DIM + lane * 8) = *(uint4*)h;
    }
    if (blockIdx.x == 0) {
        for (int i = t; i < N_CODES; i += 256) g_cnt[i] = 0.f;
        if (t == 0) g_loss = 0.0;
    }
}

// ---------------------------------------------------------------------------
// K2: per-point A (FROZEN chain), U, transposed fp16 copy. 64 pts/block.
// ---------------------------------------------------------------------------
__global__ void vq_prep_z(const float* __restrict__ z) {
    extern __shared__ float Ze[];          // [k 256][stride 68]
    const int t  = threadIdx.x;
    const int tb = blockIdx.x;
    const int b  = tb >> 7;
    const int s0 = (tb & 127) * 64;
    const float* zb = z + (size_t)b * BATCH_STRIDE + s0;

#pragma unroll
    for (int i = 0; i < 16; ++i) {
        int lin = i * 256 + t;
        int k = lin >> 4, mq = lin & 15;
        *(float4*)(Ze + k * 68 + mq * 4) = *(const float4*)(zb + (size_t)k * S_DIM + mq * 4);
    }
    __syncthreads();

    if (t < 64) {
        float a = 0.f, u = 0.f;
#pragma unroll 8
        for (int k = 0; k < 256; ++k) {
            float v = Ze[k * 68 + t];
            a = fmaf(v, v, a);              // FROZEN A chain
            u += fabsf(v);
        }
        int p = tb * 64 + t;
        g_A[p] = a;
        g_U[p] = u;
    }

    // transposed fp16 write: thread t -> pt = t>>2, k range (t&3)*64..+63
    {
        int pl = t >> 2, kq = (t & 3) * 64;
        __half* dst = g_zh + (size_t)(tb * 64 + pl) * C_DIM + kq;
#pragma unroll
        for (int cc = 0; cc < 8; ++cc) {
            int k0 = kq + cc * 8;
            __half2 h[4];
#pragma unroll
            for (int j = 0; j < 4; ++j)
                h[j] = __floats2half2_rn(Ze[(k0 + 2 * j) * 68 + pl],
                                         Ze[(k0 + 2 * j + 1) * 68 + pl]);
            *(uint4*)(dst + cc * 8) = *(uint4*)h;
        }
    }
}

// ---------------------------------------------------------------------------
// K3: fp16 HFMA2 scoring GEMM, full score dump.
// grid (512 pt-tiles, 8 code-tiles), 256 threads (16x16), microtile 8x8.
// fp32 master accumulators, fp16 sub-chains of 32 k2 (sound error bound).
// ---------------------------------------------------------------------------
__global__ void __launch_bounds__(256, 1)
vq_gemm_h() {
    extern __shared__ __half2 sh2[];
    __half2* Zs = sh2;                     // [k2 128][pt 128 +pad]
    __half2* Es = sh2 + 128 * ZPAD;        // [k2 128][code 128 +pad]

    const int t  = threadIdx.x;
    const int tx = t & 15;
    const int ty = t >> 4;
    const int pbase = blockIdx.x * 128;
    const int cbase = blockIdx.y * 128;

    // Load + transpose Z and E tiles into [k2][row] layout.
#pragma unroll
    for (int i = 0; i < 16; ++i) {
        int lin = i * 256 + t;
        int r = lin & 127, oct = lin >> 7;   // oct 0..31 -> k2 = oct*4..+3
        uint4 v = *(const uint4*)(g_zh + (size_t)(pbase + r) * C_DIM + oct * 8);
        __half2* hv = (__half2*)&v;
        Zs[(oct * 4 + 0) * ZPAD + r] = hv[0];
        Zs[(oct * 4 + 1) * ZPAD + r] = hv[1];
        Zs[(oct * 4 + 2) * ZPAD + r] = hv[2];
        Zs[(oct * 4 + 3) * ZPAD + r] = hv[3];
    }
#pragma unroll
    for (int i = 0; i < 16; ++i) {
        int lin = i * 256 + t;
        int r = lin & 127, oct = lin >> 7;
        uint4 v = *(const uint4*)(g_eh + (size_t)(cbase + r) * C_DIM + oct * 8);
        __half2* hv = (__half2*)&v;
        Es[(oct * 4 + 0) * ZPAD + r] = hv[0];
        Es[(oct * 4 + 1) * ZPAD + r] = hv[1];
        Es[(oct * 4 + 2) * ZPAD + r] = hv[2];
        Es[(oct * 4 + 3) * ZPAD + r] = hv[3];
    }
    __syncthreads();

    float macc[8][8];
#pragma unroll
    for (int p = 0; p < 8; ++p)
#pragma unroll
        for (int c = 0; c < 8; ++c) macc[p][c] = 0.f;

    const __half2 zero2 = __float2half2_rn(0.f);
#pragma unroll
    for (int qtr = 0; qtr < 4; ++qtr) {
        __half2 hacc[8][8];
#pragma unroll
        for (int p = 0; p < 8; ++p)
#pragma unroll
            for (int c = 0; c < 8; ++c) hacc[p][c] = zero2;

        for (int k2 = qtr * 32; k2 < qtr * 32 + 32; ++k2) {
            __half2 a[8], e[8];
            *(uint4*)(a)     = *(const uint4*)(Zs + k2 * ZPAD + tx * 8);
            *(uint4*)(a + 4) = *(const uint4*)(Zs + k2 * ZPAD + tx * 8 + 4);
            *(uint4*)(e)     = *(const uint4*)(Es + k2 * ZPAD + ty * 8);
            *(uint4*)(e + 4) = *(const uint4*)(Es + k2 * ZPAD + ty * 8 + 4);
#pragma unroll
            for (int p = 0; p < 8; ++p)
#pragma unroll
                for (int c = 0; c < 8; ++c)
                    hacc[p][c] = __hfma2(a[p], e[c], hacc[p][c]);
        }
#pragma unroll
        for (int p = 0; p < 8; ++p)
#pragma unroll
            for (int c = 0; c < 8; ++c) {
                float2 f = __half22float2(hacc[p][c]);
                macc[p][c] += f.x + f.y;
            }
    }

    // Epilogue: v = Bj - 2M, dump as fp16 (32B sectors, fully used).
    float Bv[8];
#pragma unroll
    for (int c = 0; c < 8; ++c) Bv[c] = __ldg(&g_e2[cbase + ty * 8 + c]);
#pragma unroll
    for (int p = 0; p < 8; ++p) {
        __half2 hv[4];
#pragma unroll
        for (int c2 = 0; c2 < 4; ++c2) {
            float v0 = fmaf(-2.f, macc[p][2 * c2],     Bv[2 * c2]);
            float v1 = fmaf(-2.f, macc[p][2 * c2 + 1], Bv[2 * c2 + 1]);
            hv[c2] = __floats2half2_rn(v0, v1);
        }
        *(uint4*)(g_v + (size_t)(pbase + tx * 8 + p) * N_CODES + cbase + ty * 8)
            = *(uint4*)hv;
    }
}

// ---------------------------------------------------------------------------
// K4: sound candidate selection from dumped scores + FROZEN exact recheck.
// ---------------------------------------------------------------------------
__global__ void vq_exact(const float* __restrict__ z,
                         const float* __restrict__ embed,
                         float* __restrict__ out) {
    extern __shared__ float Ze[];          // [k 256][m 64] (frozen layout)
    __shared__ unsigned short cand[CAND_CAP];
    __shared__ int cnt;
    __shared__ ull key[64];
    __shared__ float sA[64];

    const int t  = threadIdx.x;
    const int tb = blockIdx.x;
    const int b  = tb >> 7;
    const int s0 = (tb & 127) * 64;
    const float* zb = z + (size_t)b * BATCH_STRIDE + s0;

#pragma unroll
    for (int i = 0; i < 16; ++i) {
        int lin = i * 256 + t;
        int k = lin >> 4, mq = lin & 15;
        *(float4*)(Ze + k * 64 + mq * 4) = *(const float4*)(zb + (size_t)k * S_DIM + mq * 4);
    }
    if (t == 0) cnt = 0;
    if (t < 64) { key[t] = ~0ull; sA[t] = g_A[tb * 64 + t]; }
    __syncthreads();

    if (t < 64) {
        const int p = tb * 64 + t;
        const float A = sA[t];
        const float U = g_U[p];
        const float emax = __int_as_float(g_emax_bits);
        const __half2* vp = (const __half2*)(g_v + (size_t)p * N_CODES);

        __half2 m2 = vp[0];
#pragma unroll 8
        for (int c2 = 1; c2 < 512; ++c2) m2 = __hmin2(m2, __ldg(&vp[c2]));
        float2 mf = __half22float2(m2);
        float gmin = fminf(mf.x, mf.y);

        // sound tau: 2*eps <= 0.045*U*emax; +8e-4 covers half-dump rounding
        // and the reference's own fl32 quantization skew of d vs v.
        const float tau = gmin + fmaf(U * emax, 0.045f, 8.0e-4f);

        for (int c2 = 0; c2 < 512; ++c2) {
            float2 vf = __half22float2(__ldg(&vp[c2]));
#pragma unroll
            for (int l = 0; l < 2; ++l) {
                float v = l ? vf.y : vf.x;
                if (v <= tau) {
                    int j = 2 * c2 + l;
                    int base = atomicAdd(&cnt, 1);
                    if (base < CAND_CAP) {
                        cand[base] = (unsigned short)((t << 10) | j);
                    } else {               // overflow: inline FROZEN eval
                        float m = 0.f;
                        const float* er = embed + (size_t)j * C_DIM;
#pragma unroll 8
                        for (int k = 0; k < 256; ++k)
                            m = fmaf(Ze[k * 64 + t], __ldg(er + k), m);
                        float d = __fadd_rn(__fadd_rn(A, g_e2[j]), -2.0f * m);
                        atomicMin(&key[t], ((ull)(unsigned)__float_as_int(d) << 32) | (unsigned)j);
                    }
                }
            }
        }
    }
    __syncthreads();

    int n = min(cnt, CAND_CAP);
    for (int i = t; i < n; i += 256) {
        int e  = cand[i];
        int pl = e >> 10, j = e & 1023;
        float m = 0.f;                     // FROZEN exact chain
        const float* er = embed + (size_t)j * C_DIM;
#pragma unroll 8
        for (int k = 0; k < 256; ++k)
            m = fmaf(Ze[k * 64 + pl], __ldg(er + k), m);
        float d = __fadd_rn(__fadd_rn(sA[pl], g_e2[j]), -2.0f * m);
        // d > 0 (A ~ 256): float-bit order == numeric; low 32 = j -> lexicographic
        atomicMin(&key[pl], ((ull)(unsigned)__float_as_int(d) << 32) | (unsigned)j);
    }
    __syncthreads();

    if (t < 64) {
        int bi = (int)(key[t] & 0xFFFFFFFFull);
        int p = tb * 64 + t;
        g_idx[p] = bi;
        out[IDX_OFF + p] = (float)bi;
    }
}

// ---------------------------------------------------------------------------
// K5: z_q = fl(z + fl(e - z)), commitment loss, histogram. (FROZEN)
// ---------------------------------------------------------------------------
__global__ void vq_quantize_kernel(const float* __restrict__ z,
                                   const float* __restrict__ embed,
                                   float* __restrict__ out) {
    __shared__ int    sidx[64];
    __shared__ double red[256];

    const int t  = threadIdx.x;
    const int tb = blockIdx.x;
    const int b  = tb >> 7;
    const int s0 = (tb & 127) * 64;

    if (t < 64) {
        int id = g_idx[tb * 64 + t];
        sidx[t] = id;
        atomicAdd(&g_cnt[id], 1.0f);
    }
    __syncthreads();

    const float* zb = z   + (size_t)b * BATCH_STRIDE + s0;
    float*       qb = out + ZQ_OFF + (size_t)b * BATCH_STRIDE + s0;

    double lacc = 0.0;
#pragma unroll
    for (int i = 0; i < 16; ++i) {
        int lin = i * 256 + t;
        int c = lin >> 4, mq = lin & 15;
        float4 zv = *(const float4*)(zb + (size_t)c * S_DIM + mq * 4);
        float4 ev;
        ev.x = __ldg(embed + (size_t)sidx[mq * 4 + 0] * C_DIM + c);
        ev.y = __ldg(embed + (size_t)sidx[mq * 4 + 1] * C_DIM + c);
        ev.z = __ldg(embed + (size_t)sidx[mq * 4 + 2] * C_DIM + c);
        ev.w = __ldg(embed + (size_t)sidx[mq * 4 + 3] * C_DIM + c);
        float dx = __fadd_rn(ev.x, -zv.x);
        float dy = __fadd_rn(ev.y, -zv.y);
        float dz = __fadd_rn(ev.z, -zv.z);
        float dw = __fadd_rn(ev.w, -zv.w);
        float4 qv;
        qv.x = __fadd_rn(zv.x, dx);
        qv.y = __fadd_rn(zv.y, dy);
        qv.z = __fadd_rn(zv.z, dz);
        qv.w = __fadd_rn(zv.w, dw);
        *(float4*)(qb + (size_t)c * S_DIM + mq * 4) = qv;
        lacc += (double)(dx * dx) + (double)(dy * dy)
              + (double)(dz * dz) + (double)(dw * dw);
    }

    red[t] = lacc;
    __syncthreads();
    for (int off = 128; off > 0; off >>= 1) {
        if (t < off) red[t] += red[t + off];
        __syncthreads();
    }
    if (t == 0) atomicAdd(&g_loss, red[0]);
}

// ---------------------------------------------------------------------------
// K6: finalize loss + perplexity.
// ---------------------------------------------------------------------------
__global__ void vq_finalize_kernel(float* __restrict__ out) {
    __shared__ float sred[1024];
    int t = threadIdx.x;
    float p = g_cnt[t] * (1.0f / (float)N_PTS);
    sred[t] = p * logf(p + 1e-10f);
    __syncthreads();
    for (int off = 512; off > 0; off >>= 1) {
        if (t < off) sred[t] += sred[t + off];
        __syncthreads();
    }
    if (t == 0) {
        out[PERP_OFF] = expf(-sred[0]);
        out[LOSS_OFF] = 0.25f * (float)(g_loss / (double)Z_ELEMS);
    }
}

// ---------------------------------------------------------------------------
extern "C" void kernel_launch(void* const* d_in, const int* in_sizes, int n_in,
                              void* d_out, int out_size) {
    const float* z     = (const float*)d_in[0];
    const float* embed = (const float*)d_in[1];
    float* out = (float*)d_out;

    cudaFuncSetAttribute(vq_gemm_h, cudaFuncAttributeMaxDynamicSharedMemorySize, GEMM_SMEM);
    cudaFuncSetAttribute(vq_prep_z, cudaFuncAttributeMaxDynamicSharedMemorySize, PREPZ_SMEM);
    cudaFuncSetAttribute(vq_exact,  cudaFuncAttributeMaxDynamicSharedMemorySize, EXACT_SMEM);

    vq_prep_e<<<128, 256>>>(embed);
    vq_prep_z<<<1024, 256, PREPZ_SMEM>>>(z);
    vq_gemm_h<<<dim3(512, 8), 256, GEMM_SMEM>>>();
    vq_exact<<<1024, 256, EXACT_SMEM>>>(z, embed, out);
    vq_quantize_kernel<<<1024, 256>>>(z, embed, out);
    vq_finalize_kernel<<<1, 1024>>>(out);
}

// round 14
// speedup vs baseline: 2.9063x; 1.2492x over previous
#include <cuda_runtime.h>
#include <cuda_fp16.h>
#include <cstdint>
#include <math.h>

// Problem constants
#define B_DIM 8
#define C_DIM 256
#define S_DIM 8192
#define N_PTS 65536
#define N_CODES 1024
#define Z_ELEMS 16777216
#define BATCH_STRIDE 2097152

// Output layout (concatenated, fp32)
#define ZQ_OFF 0
#define IDX_OFF 16777216
#define LOSS_OFF 16842752
#define PERP_OFF 16842753

#define ZPAD 132                          // half2 per k2 row (128 + 4 pad)
#define GEMM_SMEM (2*128*ZPAD*4)          // Zs + Es = 135168 B
#define PREPZ_SMEM (256*68*4)             // padded fp32 [k][m] tile
#define EXACT_SMEM (256*64*4)             // fp32 [k][m] tile (frozen layout)
#define CAND_CAP 8192

typedef unsigned long long ull;

// Scratch (device globals; runtime allocation forbidden)
__device__ float    g_e2[N_CODES];        // ||e_j||^2 (frozen chain)
__device__ float    g_A[N_PTS];           // sum z^2 (frozen chain)
__device__ float    g_U[N_PTS];           // sum |z|
__device__ int      g_idx[N_PTS];
__device__ float    g_cnt[N_CODES];
__device__ double   g_loss;
__device__ int      g_emax_bits = 0;      // max over codes of max|e| (float bits)
__device__ unsigned g_vmin[N_PTS];        // per-point min score, monotonic-encoded
__device__ __half   g_zh[(size_t)N_PTS * C_DIM];    // z fp16, [pt][k]
__device__ __half   g_eh[N_CODES * C_DIM];          // e fp16, [code][k]
__device__ __half   g_v[(size_t)N_PTS * N_CODES];   // approx scores (128MB)

// monotonic float<->unsigned order encoding (works for negatives)
__device__ __forceinline__ unsigned enc_f(float v) {
    unsigned b = __float_as_uint(v);
    return b ^ ((unsigned)(((int)b) >> 31) | 0x80000000u);
}
__device__ __forceinline__ float dec_f(unsigned e) {
    unsigned b = (e & 0x80000000u) ? (e ^ 0x80000000u) : ~e;
    return __uint_as_float(b);
}

// ---------------------------------------------------------------------------
// K1: per-code ||e||^2 (FROZEN chain), fp16 copy, emax. grid 128 x 256.
// ---------------------------------------------------------------------------
__global__ void vq_prep_e(const float* __restrict__ embed) {
    int t = threadIdx.x, lane = t & 31;
    int code = blockIdx.x * 8 + (t >> 5);
    const float* row = embed + code * C_DIM;

    float s = 0.f;                         // FROZEN ||e||^2 chain
#pragma unroll
    for (int q = 0; q < 8; ++q) { float e = row[lane + q * 32]; s = fmaf(e, e, s); }
#pragma unroll
    for (int off = 16; off > 0; off >>= 1) s += __shfl_down_sync(0xffffffffu, s, off);
    if (lane == 0) g_e2[code] = s;

    float mx = 0.f;
#pragma unroll
    for (int q = 0; q < 8; ++q) mx = fmaxf(mx, fabsf(row[lane + q * 32]));
#pragma unroll
    for (int off = 16; off > 0; off >>= 1)
        mx = fmaxf(mx, __shfl_down_sync(0xffffffffu, mx, off));
    if (lane == 0) atomicMax(&g_emax_bits, __float_as_int(mx));

    {
        __half2 h[4];
#pragma unroll
        for (int j = 0; j < 4; ++j)
            h[j] = __floats2half2_rn(row[lane * 8 + 2 * j], row[lane * 8 + 2 * j + 1]);
        *(uint4*)(g_eh + (size_t)code * C_DIM + lane * 8) = *(uint4*)h;
    }
    if (blockIdx.x == 0) {
        for (int i = t; i < N_CODES; i += 256) g_cnt[i] = 0.f;
        if (t == 0) g_loss = 0.0;
    }
}

// ---------------------------------------------------------------------------
// K2: per-point A (FROZEN chain), U, transposed fp16 copy, g_vmin init.
// ---------------------------------------------------------------------------
__global__ void vq_prep_z(const float* __restrict__ z) {
    extern __shared__ float Ze[];          // [k 256][stride 68]
    const int t  = threadIdx.x;
    const int tb = blockIdx.x;
    const int b  = tb >> 7;
    const int s0 = (tb & 127) * 64;
    const float* zb = z + (size_t)b * BATCH_STRIDE + s0;

#pragma unroll
    for (int i = 0; i < 16; ++i) {
        int lin = i * 256 + t;
        int k = lin >> 4, mq = lin & 15;
        *(float4*)(Ze + k * 68 + mq * 4) = *(const float4*)(zb + (size_t)k * S_DIM + mq * 4);
    }
    __syncthreads();

    if (t < 64) {
        float a = 0.f, u = 0.f;
#pragma unroll 8
        for (int k = 0; k < 256; ++k) {
            float v = Ze[k * 68 + t];
            a = fmaf(v, v, a);              // FROZEN A chain
            u += fabsf(v);
        }
        int p = tb * 64 + t;
        g_A[p] = a;
        g_U[p] = u;
        g_vmin[p] = 0xFFFFFFFFu;            // +inf in monotonic encoding
    }

    {
        int pl = t >> 2, kq = (t & 3) * 64;
        __half* dst = g_zh + (size_t)(tb * 64 + pl) * C_DIM + kq;
#pragma unroll
        for (int cc = 0; cc < 8; ++cc) {
            int k0 = kq + cc * 8;
            __half2 h[4];
#pragma unroll
            for (int j = 0; j < 4; ++j)
                h[j] = __floats2half2_rn(Ze[(k0 + 2 * j) * 68 + pl],
                                         Ze[(k0 + 2 * j + 1) * 68 + pl]);
            *(uint4*)(dst + cc * 8) = *(uint4*)h;
        }
    }
}

// ---------------------------------------------------------------------------
// K3: fp16 HFMA2 scoring GEMM, full score dump + per-point block min.
// grid (512 pt-tiles, 8 code-tiles), 256 threads (16x16), microtile 8x8.
// ---------------------------------------------------------------------------
__global__ void __launch_bounds__(256, 1)
vq_gemm_h() {
    extern __shared__ __half2 sh2[];
    __half2* Zs = sh2;                     // [k2 128][pt 128 +pad]
    __half2* Es = sh2 + 128 * ZPAD;        // [k2 128][code 128 +pad]

    const int t  = threadIdx.x;
    const int tx = t & 15;
    const int ty = t >> 4;
    const int pbase = blockIdx.x * 128;
    const int cbase = blockIdx.y * 128;

#pragma unroll
    for (int i = 0; i < 16; ++i) {
        int lin = i * 256 + t;
        int r = lin & 127, oct = lin >> 7;
        uint4 v = *(const uint4*)(g_zh + (size_t)(pbase + r) * C_DIM + oct * 8);
        __half2* hv = (__half2*)&v;
        Zs[(oct * 4 + 0) * ZPAD + r] = hv[0];
        Zs[(oct * 4 + 1) * ZPAD + r] = hv[1];
        Zs[(oct * 4 + 2) * ZPAD + r] = hv[2];
        Zs[(oct * 4 + 3) * ZPAD + r] = hv[3];
    }
#pragma unroll
    for (int i = 0; i < 16; ++i) {
        int lin = i * 256 + t;
        int r = lin & 127, oct = lin >> 7;
        uint4 v = *(const uint4*)(g_eh + (size_t)(cbase + r) * C_DIM + oct * 8);
        __half2* hv = (__half2*)&v;
        Es[(oct * 4 + 0) * ZPAD + r] = hv[0];
        Es[(oct * 4 + 1) * ZPAD + r] = hv[1];
        Es[(oct * 4 + 2) * ZPAD + r] = hv[2];
        Es[(oct * 4 + 3) * ZPAD + r] = hv[3];
    }
    __syncthreads();

    float macc[8][8];
#pragma unroll
    for (int p = 0; p < 8; ++p)
#pragma unroll
        for (int c = 0; c < 8; ++c) macc[p][c] = 0.f;

    const __half2 zero2 = __float2half2_rn(0.f);
#pragma unroll
    for (int qtr = 0; qtr < 4; ++qtr) {
        __half2 hacc[8][8];
#pragma unroll
        for (int p = 0; p < 8; ++p)
#pragma unroll
            for (int c = 0; c < 8; ++c) hacc[p][c] = zero2;

        for (int k2 = qtr * 32; k2 < qtr * 32 + 32; ++k2) {
            __half2 a[8], e[8];
            *(uint4*)(a)     = *(const uint4*)(Zs + k2 * ZPAD + tx * 8);
            *(uint4*)(a + 4) = *(const uint4*)(Zs + k2 * ZPAD + tx * 8 + 4);
            *(uint4*)(e)     = *(const uint4*)(Es + k2 * ZPAD + ty * 8);
            *(uint4*)(e + 4) = *(const uint4*)(Es + k2 * ZPAD + ty * 8 + 4);
#pragma unroll
            for (int p = 0; p < 8; ++p)
#pragma unroll
                for (int c = 0; c < 8; ++c)
                    hacc[p][c] = __hfma2(a[p], e[c], hacc[p][c]);
        }
#pragma unroll
        for (int p = 0; p < 8; ++p)
#pragma unroll
            for (int c = 0; c < 8; ++c) {
                float2 f = __half22float2(hacc[p][c]);
                macc[p][c] += f.x + f.y;
            }
    }

    // Epilogue: v = Bj - 2M (float), per-pt min, fp16 dump.
    float Bv[8];
#pragma unroll
    for (int c = 0; c < 8; ++c) Bv[c] = __ldg(&g_e2[cbase + ty * 8 + c]);
    float vmin[8];
#pragma unroll
    for (int p = 0; p < 8; ++p) {
        float v[8];
#pragma unroll
        for (int c = 0; c < 8; ++c) v[c] = fmaf(-2.f, macc[p][c], Bv[c]);
        float mn = v[0];
#pragma unroll
        for (int c = 1; c < 8; ++c) mn = fminf(mn, v[c]);
        vmin[p] = mn;
        __half2 hv[4];
#pragma unroll
        for (int c2 = 0; c2 < 4; ++c2)
            hv[c2] = __floats2half2_rn(v[2 * c2], v[2 * c2 + 1]);
        *(uint4*)(g_v + (size_t)(pbase + tx * 8 + p) * N_CODES + cbase + ty * 8)
            = *(uint4*)hv;
    }

    // Block-level per-point min -> global atomicMin (monotonic encoding).
    __syncthreads();
    float* sred = (float*)sh2;             // 128 pts x 16 ty
#pragma unroll
    for (int p = 0; p < 8; ++p) sred[(tx * 8 + p) * 16 + ty] = vmin[p];
    __syncthreads();
    if (t < 128) {
        float m = sred[t * 16];
#pragma unroll
        for (int y = 1; y < 16; ++y) m = fminf(m, sred[t * 16 + y]);
        atomicMin(&g_vmin[pbase + t], enc_f(m));
    }
}

// ---------------------------------------------------------------------------
// K4: parallel threshold scan + FROZEN exact recheck.
// ---------------------------------------------------------------------------
__global__ void vq_exact(const float* __restrict__ z,
                         const float* __restrict__ embed,
                         float* __restrict__ out) {
    extern __shared__ float Ze[];          // [k 256][m 64] (frozen layout)
    __shared__ unsigned short cand[CAND_CAP];
    __shared__ int cnt;
    __shared__ ull key[64];
    __shared__ float sA[64], sTau[64];

    const int t  = threadIdx.x;
    const int tb = blockIdx.x;
    const int b  = tb >> 7;
    const int s0 = (tb & 127) * 64;
    const float* zb = z + (size_t)b * BATCH_STRIDE + s0;

#pragma unroll
    for (int i = 0; i < 16; ++i) {
        int lin = i * 256 + t;
        int k = lin >> 4, mq = lin & 15;
        *(float4*)(Ze + k * 64 + mq * 4) = *(const float4*)(zb + (size_t)k * S_DIM + mq * 4);
    }
    if (t == 0) cnt = 0;
    if (t < 64) {
        int p = tb * 64 + t;
        key[t] = ~0ull;
        sA[t] = g_A[p];
        float gmin = dec_f(g_vmin[p]);     // exact float min of approx scores
        float U = g_U[p];
        float emax = __int_as_float(g_emax_bits);
        // sound: 2*eps(fp16 path) <= 0.045*U*emax; slack 1.2e-3 covers the
        // fp16 dump rounding of candidates (gmin is pre-rounding) + ref skew.
        sTau[t] = gmin + fmaf(U * emax, 0.045f, 1.2e-3f);
    }
    __syncthreads();

    // Parallel scan: 4 threads per point, 256 contiguous codes each.
    {
        const int pl = t >> 2, q = t & 3;
        const int p = tb * 64 + pl;
        const float tau = sTau[pl];
        const uint4* vp = (const uint4*)(g_v + (size_t)p * N_CODES + q * 256);
#pragma unroll 4
        for (int i = 0; i < 32; ++i) {
            uint4 u = __ldg(&vp[i]);
            __half2 h0 = *(__half2*)&u.x, h1 = *(__half2*)&u.y;
            __half2 h2 = *(__half2*)&u.z, h3 = *(__half2*)&u.w;
            __half2 m = __hmin2(__hmin2(h0, h1), __hmin2(h2, h3));
            float mn = fminf(__low2float(m), __high2float(m));
            if (mn <= tau) {
                float vf[8];
                vf[0] = __low2float(h0); vf[1] = __high2float(h0);
                vf[2] = __low2float(h1); vf[3] = __high2float(h1);
                vf[4] = __low2float(h2); vf[5] = __high2float(h2);
                vf[6] = __low2float(h3); vf[7] = __high2float(h3);
#pragma unroll
                for (int l = 0; l < 8; ++l) {
                    if (vf[l] <= tau) {
                        int j = q * 256 + i * 8 + l;
                        int base = atomicAdd(&cnt, 1);
                        if (base < CAND_CAP) {
                            cand[base] = (unsigned short)((pl << 10) | j);
                        } else {           // overflow: inline FROZEN eval
                            float mm = 0.f;
                            const float* er = embed + (size_t)j * C_DIM;
#pragma unroll 8
                            for (int k = 0; k < 256; ++k)
                                mm = fmaf(Ze[k * 64 + pl], __ldg(er + k), mm);
                            float d = __fadd_rn(__fadd_rn(sA[pl], g_e2[j]), -2.0f * mm);
                            atomicMin(&key[pl],
                                ((ull)(unsigned)__float_as_int(d) << 32) | (unsigned)j);
                        }
                    }
                }
            }
        }
    }
    __syncthreads();

    int n = min(cnt, CAND_CAP);
    for (int i = t; i < n; i += 256) {
        int e  = cand[i];
        int pl = e >> 10, j = e & 1023;
        float m = 0.f;                     // FROZEN exact chain
        const float* er = embed + (size_t)j * C_DIM;
#pragma unroll 8
        for (int k = 0; k < 256; ++k)
            m = fmaf(Ze[k * 64 + pl], __ldg(er + k), m);
        float d = __fadd_rn(__fadd_rn(sA[pl], g_e2[j]), -2.0f * m);
        // d > 0 (A ~ 256): float-bit order == numeric; low 32 = j -> lexicographic
        atomicMin(&key[pl], ((ull)(unsigned)__float_as_int(d) << 32) | (unsigned)j);
    }
    __syncthreads();

    if (t < 64) {
        int bi = (int)(key[t] & 0xFFFFFFFFull);
        int p = tb * 64 + t;
        g_idx[p] = bi;
        out[IDX_OFF + p] = (float)bi;
    }
}

// ---------------------------------------------------------------------------
// K5: z_q = fl(z + fl(e - z)), commitment loss, histogram. (FROZEN)
// ---------------------------------------------------------------------------
__global__ void vq_quantize_kernel(const float* __restrict__ z,
                                   const float* __restrict__ embed,
                                   float* __restrict__ out) {
    __shared__ int    sidx[64];
    __shared__ double red[256];

    const int t  = threadIdx.x;
    const int tb = blockIdx.x;
    const int b  = tb >> 7;
    const int s0 = (tb & 127) * 64;

    if (t < 64) {
        int id = g_idx[tb * 64 + t];
        sidx[t] = id;
        atomicAdd(&g_cnt[id], 1.0f);
    }
    __syncthreads();

    const float* zb = z   + (size_t)b * BATCH_STRIDE + s0;
    float*       qb = out + ZQ_OFF + (size_t)b * BATCH_STRIDE + s0;

    double lacc = 0.0;
#pragma unroll
    for (int i = 0; i < 16; ++i) {
        int lin = i * 256 + t;
        int c = lin >> 4, mq = lin & 15;
        float4 zv = *(const float4*)(zb + (size_t)c * S_DIM + mq * 4);
        float4 ev;
        ev.x = __ldg(embed + (size_t)sidx[mq * 4 + 0] * C_DIM + c);
        ev.y = __ldg(embed + (size_t)sidx[mq * 4 + 1] * C_DIM + c);
        ev.z = __ldg(embed + (size_t)sidx[mq * 4 + 2] * C_DIM + c);
        ev.w = __ldg(embed + (size_t)sidx[mq * 4 + 3] * C_DIM + c);
        float dx = __fadd_rn(ev.x, -zv.x);
        float dy = __fadd_rn(ev.y, -zv.y);
        float dz = __fadd_rn(ev.z, -zv.z);
        float dw = __fadd_rn(ev.w, -zv.w);
        float4 qv;
        qv.x = __fadd_rn(zv.x, dx);
        qv.y = __fadd_rn(zv.y, dy);
        qv.z = __fadd_rn(zv.z, dz);
        qv.w = __fadd_rn(zv.w, dw);
        *(float4*)(qb + (size_t)c * S_DIM + mq * 4) = qv;
        lacc += (double)(dx * dx) + (double)(dy * dy)
              + (double)(dz * dz) + (double)(dw * dw);
    }

    red[t] = lacc;
    __syncthreads();
    for (int off = 128; off > 0; off >>= 1) {
        if (t < off) red[t] += red[t + off];
        __syncthreads();
    }
    if (t == 0) atomicAdd(&g_loss, red[0]);
}

// ---------------------------------------------------------------------------
// K6: finalize loss + perplexity.
// ---------------------------------------------------------------------------
__global__ void vq_finalize_kernel(float* __restrict__ out) {
    __shared__ float sred[1024];
    int t = threadIdx.x;
    float p = g_cnt[t] * (1.0f / (float)N_PTS);
    sred[t] = p * logf(p + 1e-10f);
    __syncthreads();
    for (int off = 512; off > 0; off >>= 1) {
        if (t < off) sred[t] += sred[t + off];
        __syncthreads();
    }
    if (t == 0) {
        out[PERP_OFF] = expf(-sred[0]);
        out[LOSS_OFF] = 0.25f * (float)(g_loss / (double)Z_ELEMS);
    }
}

// ---------------------------------------------------------------------------
extern "C" void kernel_launch(void* const* d_in, const int* in_sizes, int n_in,
                              void* d_out, int out_size) {
    const float* z     = (const float*)d_in[0];
    const float* embed = (const float*)d_in[1];
    float* out = (float*)d_out;

    cudaFuncSetAttribute(vq_gemm_h, cudaFuncAttributeMaxDynamicSharedMemorySize, GEMM_SMEM);
    cudaFuncSetAttribute(vq_prep_z, cudaFuncAttributeMaxDynamicSharedMemorySize, PREPZ_SMEM);
    cudaFuncSetAttribute(vq_exact,  cudaFuncAttributeMaxDynamicSharedMemorySize, EXACT_SMEM);

    vq_prep_e<<<128, 256>>>(embed);
    vq_prep_z<<<1024, 256, PREPZ_SMEM>>>(z);
    vq_gemm_h<<<dim3(512, 8), 256, GEMM_SMEM>>>();
    vq_exact<<<1024, 256, EXACT_SMEM>>>(z, embed, out);
    vq_quantize_kernel<<<1024, 256>>>(z, embed, out);
    vq_finalize_kernel<<<1, 1024>>>(out);
}

// round 15
// speedup vs baseline: 3.0799x; 1.0597x over previous
#include <cuda_runtime.h>
#include <cuda_fp16.h>
#include <cstdint>
#include <math.h>

// Problem constants
#define B_DIM 8
#define C_DIM 256
#define S_DIM 8192
#define N_PTS 65536
#define N_CODES 1024
#define Z_ELEMS 16777216
#define BATCH_STRIDE 2097152

// Output layout (concatenated, fp32)
#define ZQ_OFF 0
#define IDX_OFF 16777216
#define LOSS_OFF 16842752
#define PERP_OFF 16842753

#define ZPAD 132                          // half2 per smem k2 row (128 + 4 pad)
#define VROW 136                          // halves per vtile row (272B = 17*16)
#define GEMM_SMEM (2*128*ZPAD*4)          // Zs + Es = 135168 B
#define PREPZ_SMEM (256*68*4)             // padded fp32 [k][m] tile
#define EXACT_SMEM (256*64*4)             // fp32 [k][m] tile (frozen layout)
#define SCAP 4096                         // candidates per 64-pt group

typedef unsigned long long ull;

// Scratch (device globals; runtime allocation forbidden)
__device__ float    g_e2[N_CODES];        // ||e_j||^2 (frozen chain)
__device__ float    g_A[N_PTS];           // sum z^2 (frozen chain)
__device__ float    g_U[N_PTS];           // sum |z|
__device__ float    g_cnt[N_CODES];
__device__ double   g_loss;
__device__ int      g_emax_bits = 0;      // max over codes of max|e| (float bits)
__device__ unsigned g_vmin[N_PTS];        // per-point min score, monotonic-encoded
__device__ __half2  g_zhT[(size_t)N_PTS * 128];   // z fp16 [tile512][k2 128][pt 128]
__device__ __half2  g_ehT[128 * N_CODES];         // e fp16 [k2 128][code 1024]
__device__ __half   g_v[(size_t)N_PTS * N_CODES]; // approx scores (128MB)
__device__ int      g_ccnt[1024];                 // per-group candidate counts
__device__ unsigned short g_cand[1024 * SCAP];    // per-group candidates (pl<<10|j)

// monotonic float<->unsigned order encoding
__device__ __forceinline__ unsigned enc_f(float v) {
    unsigned b = __float_as_uint(v);
    return b ^ ((unsigned)(((int)b) >> 31) | 0x80000000u);
}
__device__ __forceinline__ float dec_f(unsigned e) {
    unsigned b = (e & 0x80000000u) ? (e ^ 0x80000000u) : ~e;
    return __uint_as_float(b);
}

// ---------------------------------------------------------------------------
// K1: per-code ||e||^2 (FROZEN chain), emax, zero accumulators.
// ---------------------------------------------------------------------------
__global__ void vq_prep_e(const float* __restrict__ embed) {
    int t = threadIdx.x, lane = t & 31;
    int code = blockIdx.x * 8 + (t >> 5);
    const float* row = embed + code * C_DIM;

    float s = 0.f;                         // FROZEN ||e||^2 chain
#pragma unroll
    for (int q = 0; q < 8; ++q) { float e = row[lane + q * 32]; s = fmaf(e, e, s); }
#pragma unroll
    for (int off = 16; off > 0; off >>= 1) s += __shfl_down_sync(0xffffffffu, s, off);
    if (lane == 0) g_e2[code] = s;

    float mx = 0.f;
#pragma unroll
    for (int q = 0; q < 8; ++q) mx = fmaxf(mx, fabsf(row[lane + q * 32]));
#pragma unroll
    for (int off = 16; off > 0; off >>= 1)
        mx = fmaxf(mx, __shfl_down_sync(0xffffffffu, mx, off));
    if (lane == 0) atomicMax(&g_emax_bits, __float_as_int(mx));

    if (blockIdx.x == 0) {
        for (int i = t; i < N_CODES; i += 256) { g_cnt[i] = 0.f; g_ccnt[i] = 0; }
        if (t == 0) g_loss = 0.0;
    }
}

// ---------------------------------------------------------------------------
// K1b: e -> transposed half2 [k2][code]. grid 128 x 256.
// ---------------------------------------------------------------------------
__global__ void vq_transpose_e(const float* __restrict__ embed) {
    int k2 = blockIdx.x;
    for (int c = threadIdx.x; c < N_CODES; c += 256) {
        float lo = __ldg(embed + (size_t)c * C_DIM + 2 * k2);
        float hi = __ldg(embed + (size_t)c * C_DIM + 2 * k2 + 1);
        g_ehT[k2 * N_CODES + c] = __floats2half2_rn(lo, hi);
    }
}

// ---------------------------------------------------------------------------
// K2: per-point A (FROZEN), U, vmin init, transposed half2 z [tile][k2][pt].
// ---------------------------------------------------------------------------
__global__ void vq_prep_z(const float* __restrict__ z) {
    extern __shared__ float Ze[];          // [k 256][stride 68]
    const int t  = threadIdx.x;
    const int tb = blockIdx.x;
    const int b  = tb >> 7;
    const int s0 = (tb & 127) * 64;
    const float* zb = z + (size_t)b * BATCH_STRIDE + s0;

#pragma unroll
    for (int i = 0; i < 16; ++i) {
        int lin = i * 256 + t;
        int k = lin >> 4, mq = lin & 15;
        *(float4*)(Ze + k * 68 + mq * 4) = *(const float4*)(zb + (size_t)k * S_DIM + mq * 4);
    }
    __syncthreads();

    if (t < 64) {
        float a = 0.f, u = 0.f;
#pragma unroll 8
        for (int k = 0; k < 256; ++k) {
            float v = Ze[k * 68 + t];
            a = fmaf(v, v, a);              // FROZEN A chain
            u += fabsf(v);
        }
        int p = tb * 64 + t;
        g_A[p] = a;
        g_U[p] = u;
        g_vmin[p] = 0xFFFFFFFFu;
    }

    // transposed half2 write: 128 k2 x 64 pts, coalesced
    const int tile = tb >> 1, moff = (tb & 1) * 64;
#pragma unroll
    for (int i = 0; i < 32; ++i) {
        int lin = i * 256 + t;
        int k2 = lin >> 6, pl = lin & 63;
        g_zhT[(size_t)tile * 16384 + k2 * 128 + moff + pl] =
            __floats2half2_rn(Ze[(2 * k2) * 68 + pl], Ze[(2 * k2 + 1) * 68 + pl]);
    }
}

// ---------------------------------------------------------------------------
// K3: fp16 HFMA2 scoring GEMM. grid (512 pt-tiles, 8 code-tiles), 256 thr.
// Quad microtile: pts {tx*4+i, 64+tx*4+i}, codes {ty*4+c, 64+ty*4+c}.
// Conflict-free LDS, coalesced tile loads, smem-staged coalesced dump.
// ---------------------------------------------------------------------------
__global__ void __launch_bounds__(256, 1)
vq_gemm_h() {
    extern __shared__ __half2 sh2[];
    __half2* Zs = sh2;                     // [k2][ZPAD]
    __half2* Es = sh2 + 128 * ZPAD;

    const int t  = threadIdx.x;
    const int tx = t & 15;
    const int ty = t >> 4;
    const int pbase = blockIdx.x * 128;
    const int cbase = blockIdx.y * 128;

    const __half2* gz = g_zhT + (size_t)blockIdx.x * 16384;
#pragma unroll
    for (int i = 0; i < 16; ++i) {
        int lin = i * 256 + t, k2 = lin >> 5, q = lin & 31;
        *(uint4*)(Zs + k2 * ZPAD + q * 4) = *(const uint4*)(gz + k2 * 128 + q * 4);
    }
#pragma unroll
    for (int i = 0; i < 16; ++i) {
        int lin = i * 256 + t, k2 = lin >> 5, q = lin & 31;
        *(uint4*)(Es + k2 * ZPAD + q * 4) =
            *(const uint4*)(g_ehT + k2 * N_CODES + cbase + q * 4);
    }
    __syncthreads();

    float macc[2][4][2][4];
#pragma unroll
    for (int pg = 0; pg < 2; ++pg)
#pragma unroll
        for (int i = 0; i < 4; ++i)
#pragma unroll
            for (int cg = 0; cg < 2; ++cg)
#pragma unroll
                for (int c = 0; c < 4; ++c) macc[pg][i][cg][c] = 0.f;

    const __half2 zero2 = __float2half2_rn(0.f);
#pragma unroll
    for (int qtr = 0; qtr < 4; ++qtr) {
        __half2 hacc[2][4][2][4];
#pragma unroll
        for (int pg = 0; pg < 2; ++pg)
#pragma unroll
            for (int i = 0; i < 4; ++i)
#pragma unroll
                for (int cg = 0; cg < 2; ++cg)
#pragma unroll
                    for (int c = 0; c < 4; ++c) hacc[pg][i][cg][c] = zero2;

        for (int k2 = qtr * 32; k2 < qtr * 32 + 32; ++k2) {
            __half2 a[2][4], e[2][4];
            *(uint4*)&a[0][0] = *(const uint4*)(Zs + k2 * ZPAD + tx * 4);
            *(uint4*)&a[1][0] = *(const uint4*)(Zs + k2 * ZPAD + 64 + tx * 4);
            *(uint4*)&e[0][0] = *(const uint4*)(Es + k2 * ZPAD + ty * 4);
            *(uint4*)&e[1][0] = *(const uint4*)(Es + k2 * ZPAD + 64 + ty * 4);
#pragma unroll
            for (int pg = 0; pg < 2; ++pg)
#pragma unroll
                for (int i = 0; i < 4; ++i)
#pragma unroll
                    for (int cg = 0; cg < 2; ++cg)
#pragma unroll
                        for (int c = 0; c < 4; ++c)
                            hacc[pg][i][cg][c] =
                                __hfma2(a[pg][i], e[cg][c], hacc[pg][i][cg][c]);
        }
#pragma unroll
        for (int pg = 0; pg < 2; ++pg)
#pragma unroll
            for (int i = 0; i < 4; ++i)
#pragma unroll
                for (int cg = 0; cg < 2; ++cg)
#pragma unroll
                    for (int c = 0; c < 4; ++c) {
                        float2 f = __half22float2(hacc[pg][i][cg][c]);
                        macc[pg][i][cg][c] += f.x + f.y;
                    }
    }
    __syncthreads();                       // done reading Zs/Es

    __half* vtile = (__half*)Es;           // [128][VROW]
    float*  sred  = (float*)Zs;            // [128][16]

    float Bv[2][4];
#pragma unroll
    for (int cg = 0; cg < 2; ++cg)
#pragma unroll
        for (int c = 0; c < 4; ++c)
            Bv[cg][c] = __ldg(&g_e2[cbase + cg * 64 + ty * 4 + c]);

#pragma unroll
    for (int pg = 0; pg < 2; ++pg)
#pragma unroll
        for (int i = 0; i < 4; ++i) {
            int pl = pg * 64 + tx * 4 + i;
            float vmn = INFINITY;
#pragma unroll
            for (int cg = 0; cg < 2; ++cg) {
                float v0 = fmaf(-2.f, macc[pg][i][cg][0], Bv[cg][0]);
                float v1 = fmaf(-2.f, macc[pg][i][cg][1], Bv[cg][1]);
                float v2 = fmaf(-2.f, macc[pg][i][cg][2], Bv[cg][2]);
                float v3 = fmaf(-2.f, macc[pg][i][cg][3], Bv[cg][3]);
                vmn = fminf(vmn, fminf(fminf(v0, v1), fminf(v2, v3)));
                __half2 h01 = __floats2half2_rn(v0, v1);
                __half2 h23 = __floats2half2_rn(v2, v3);
                uint2 w;
                w.x = *(unsigned*)&h01;
                w.y = *(unsigned*)&h23;
                *(uint2*)(vtile + pl * VROW + cg * 64 + ty * 4) = w;
            }
            sred[pl * 16 + ty] = vmn;
        }
    __syncthreads();

    if (t < 128) {
        float m = sred[t * 16];
#pragma unroll
        for (int y = 1; y < 16; ++y) m = fminf(m, sred[t * 16 + y]);
        atomicMin(&g_vmin[pbase + t], enc_f(m));
    }

    // coalesced dump: 128 rows x 256B
#pragma unroll
    for (int i = 0; i < 8; ++i) {
        int lin = i * 256 + t, row = lin >> 4, qq = lin & 15;
        *(uint4*)(g_v + (size_t)(pbase + row) * N_CODES + cbase + qq * 8) =
            *(uint4*)(vtile + row * VROW + qq * 8);
    }
}

// ---------------------------------------------------------------------------
// K4: threshold scan, warp per point, fully coalesced. grid 8192 x 256.
// ---------------------------------------------------------------------------
__global__ void vq_scan() {
    const int t = threadIdx.x;
    const int w = t >> 5, l = t & 31;
    const int p = blockIdx.x * 8 + w;

    float gmin = dec_f(g_vmin[p]);
    // sound tau (validated R14): 2*eps <= 0.045*U*emax; 1.2e-3 slack covers
    // fp16 dump rounding of candidates + reference fl32 skew.
    const float tau = gmin +
        fmaf(g_U[p] * __int_as_float(g_emax_bits), 0.045f, 1.2e-3f);

    const int grp = p >> 6, pl = p & 63;
    const uint4* vp = (const uint4*)(g_v + (size_t)p * N_CODES);
#pragma unroll
    for (int i = 0; i < 4; ++i) {
        uint4 u = __ldg(&vp[l + 32 * i]);
        __half2 h0 = *(__half2*)&u.x, h1 = *(__half2*)&u.y;
        __half2 h2 = *(__half2*)&u.z, h3 = *(__half2*)&u.w;
        __half2 m = __hmin2(__hmin2(h0, h1), __hmin2(h2, h3));
        float mn = fminf(__low2float(m), __high2float(m));
        if (mn <= tau) {
            float vf[8];
            vf[0] = __low2float(h0); vf[1] = __high2float(h0);
            vf[2] = __low2float(h1); vf[3] = __high2float(h1);
            vf[4] = __low2float(h2); vf[5] = __high2float(h2);
            vf[6] = __low2float(h3); vf[7] = __high2float(h3);
#pragma unroll
            for (int s = 0; s < 8; ++s) {
                if (vf[s] <= tau) {
                    int j = (l + 32 * i) * 8 + s;
                    int base = atomicAdd(&g_ccnt[grp], 1);
                    if (base < SCAP)
                        g_cand[grp * SCAP + base] = (unsigned short)((pl << 10) | j);
                }
            }
        }
    }
}

// ---------------------------------------------------------------------------
// K5: exact (FROZEN) recheck + fused quantize/loss/histogram. grid 1024.
// ---------------------------------------------------------------------------
__global__ void vq_exact_q(const float* __restrict__ z,
                           const float* __restrict__ embed,
                           float* __restrict__ out) {
    extern __shared__ float Ze[];          // [k 256][m 64] (frozen layout)
    __shared__ ull    key[64];
    __shared__ float  sA[64];
    __shared__ int    sidx[64];
    __shared__ double red[256];

    const int t  = threadIdx.x;
    const int tb = blockIdx.x;
    const int b  = tb >> 7;
    const int s0 = (tb & 127) * 64;
    const float* zb = z + (size_t)b * BATCH_STRIDE + s0;

#pragma unroll
    for (int i = 0; i < 16; ++i) {
        int lin = i * 256 + t;
        int k = lin >> 4, mq = lin & 15;
        *(float4*)(Ze + k * 64 + mq * 4) = *(const float4*)(zb + (size_t)k * S_DIM + mq * 4);
    }
    if (t < 64) { key[t] = ~0ull; sA[t] = g_A[tb * 64 + t]; }
    __syncthreads();

    const int ncand = g_ccnt[tb];
    if (ncand <= SCAP) {
        for (int i = t; i < ncand; i += 256) {
            int e  = g_cand[tb * SCAP + i];
            int pl = e >> 10, j = e & 1023;
            float m = 0.f;                 // FROZEN exact chain
            const float* er = embed + (size_t)j * C_DIM;
#pragma unroll 8
            for (int k = 0; k < 256; ++k)
                m = fmaf(Ze[k * 64 + pl], __ldg(er + k), m);
            float d = __fadd_rn(__fadd_rn(sA[pl], g_e2[j]), -2.0f * m);
            atomicMin(&key[pl], ((ull)(unsigned)__float_as_int(d) << 32) | (unsigned)j);
        }
    } else {                               // overflow: deterministic full eval
        for (int i = t; i < 64 * 1024; i += 256) {
            int pl = i >> 10, j = i & 1023;
            float m = 0.f;
            const float* er = embed + (size_t)j * C_DIM;
#pragma unroll 8
            for (int k = 0; k < 256; ++k)
                m = fmaf(Ze[k * 64 + pl], __ldg(er + k), m);
            float d = __fadd_rn(__fadd_rn(sA[pl], g_e2[j]), -2.0f * m);
            atomicMin(&key[pl], ((ull)(unsigned)__float_as_int(d) << 32) | (unsigned)j);
        }
    }
    __syncthreads();

    if (t < 64) {
        int bi = (int)(key[t] & 0xFFFFFFFFull);
        sidx[t] = bi;
        out[IDX_OFF + tb * 64 + t] = (float)bi;
        atomicAdd(&g_cnt[bi], 1.0f);
    }
    __syncthreads();

    // fused quantize (FROZEN arithmetic), z read from Ze
    float* qb = out + ZQ_OFF + (size_t)b * BATCH_STRIDE + s0;
    double lacc = 0.0;
#pragma unroll
    for (int i = 0; i < 16; ++i) {
        int lin = i * 256 + t;
        int c = lin >> 4, mq = lin & 15;
        float4 zv = *(const float4*)(Ze + c * 64 + mq * 4);
        float4 ev;
        ev.x = __ldg(embed + (size_t)sidx[mq * 4 + 0] * C_DIM + c);
        ev.y = __ldg(embed + (size_t)sidx[mq * 4 + 1] * C_DIM + c);
        ev.z = __ldg(embed + (size_t)sidx[mq * 4 + 2] * C_DIM + c);
        ev.w = __ldg(embed + (size_t)sidx[mq * 4 + 3] * C_DIM + c);
        float dx = __fadd_rn(ev.x, -zv.x);
        float dy = __fadd_rn(ev.y, -zv.y);
        float dz = __fadd_rn(ev.z, -zv.z);
        float dw = __fadd_rn(ev.w, -zv.w);
        float4 qv;
        qv.x = __fadd_rn(zv.x, dx);
        qv.y = __fadd_rn(zv.y, dy);
        qv.z = __fadd_rn(zv.z, dz);
        qv.w = __fadd_rn(zv.w, dw);
        *(float4*)(qb + (size_t)c * S_DIM + mq * 4) = qv;
        lacc += (double)(dx * dx) + (double)(dy * dy)
              + (double)(dz * dz) + (double)(dw * dw);
    }

    red[t] = lacc;
    __syncthreads();
    for (int off = 128; off > 0; off >>= 1) {
        if (t < off) red[t] += red[t + off];
        __syncthreads();
    }
    if (t == 0) atomicAdd(&g_loss, red[0]);
}

// ---------------------------------------------------------------------------
// K6: finalize loss + perplexity.
// ---------------------------------------------------------------------------
__global__ void vq_finalize_kernel(float* __restrict__ out) {
    __shared__ float sred[1024];
    int t = threadIdx.x;
    float p = g_cnt[t] * (1.0f / (float)N_PTS);
    sred[t] = p * logf(p + 1e-10f);
    __syncthreads();
    for (int off = 512; off > 0; off >>= 1) {
        if (t < off) sred[t] += sred[t + off];
        __syncthreads();
    }
    if (t == 0) {
        out[PERP_OFF] = expf(-sred[0]);
        out[LOSS_OFF] = 0.25f * (float)(g_loss / (double)Z_ELEMS);
    }
}

// ---------------------------------------------------------------------------
extern "C" void kernel_launch(void* const* d_in, const int* in_sizes, int n_in,
                              void* d_out, int out_size) {
    const float* z     = (const float*)d_in[0];
    const float* embed = (const float*)d_in[1];
    float* out = (float*)d_out;

    cudaFuncSetAttribute(vq_gemm_h,  cudaFuncAttributeMaxDynamicSharedMemorySize, GEMM_SMEM);
    cudaFuncSetAttribute(vq_prep_z,  cudaFuncAttributeMaxDynamicSharedMemorySize, PREPZ_SMEM);
    cudaFuncSetAttribute(vq_exact_q, cudaFuncAttributeMaxDynamicSharedMemorySize, EXACT_SMEM);

    vq_prep_e<<<128, 256>>>(embed);
    vq_transpose_e<<<128, 256>>>(embed);
    vq_prep_z<<<1024, 256, PREPZ_SMEM>>>(z);
    vq_gemm_h<<<dim3(512, 8), 256, GEMM_SMEM>>>();
    vq_scan<<<8192, 256>>>();
    vq_exact_q<<<1024, 256, EXACT_SMEM>>>(z, embed, out);
    vq_finalize_kernel<<<1, 1024>>>(out);
}